// round 14
// baseline (speedup 1.0000x reference)
#include <cuda_runtime.h>
#include <cuda_bf16.h>
#include <cstdint>

// Problem constants
#define Bn 8
#define Nn 1024
#define Dn 512
#define Hn 8
#define DHn 64
#define BHn (Bn*Hn)          // 64
#define SCALE 0.125f         // 1/sqrt(64)

typedef unsigned long long ull;

__device__ __forceinline__ ull pk2(float lo, float hi) {
    ull r; asm("mov.b64 %0, {%1,%2};" : "=l"(r) : "f"(lo), "f"(hi)); return r;
}
__device__ __forceinline__ ull fma2(ull a, ull b, ull c) {
    ull d; asm("fma.rn.f32x2 %0, %1, %2, %3;" : "=l"(d) : "l"(a), "l"(b), "l"(c)); return d;
}
__device__ __forceinline__ ull add2(ull a, ull b) {
    ull d; asm("add.rn.f32x2 %0, %1, %2;" : "=l"(d) : "l"(a), "l"(b)); return d;
}
__device__ __forceinline__ float2 unpk(ull v) {
    float2 f; asm("mov.b64 {%0,%1}, %2;" : "=f"(f.x), "=f"(f.y) : "l"(v)); return f;
}
__device__ __forceinline__ uint32_t smem_u32(const void* p) {
    uint32_t a;
    asm("{ .reg .u64 t; cvta.to.shared.u64 t, %1; cvt.u32.u64 %0, t; }" : "=r"(a) : "l"(p));
    return a;
}

// Scratch (allocation-free rule: __device__ globals). Layout: [b, n, H*dh] = [8192, 512]
__device__ float g_q[(size_t)Bn*Nn*Dn];
__device__ float g_k[(size_t)Bn*Nn*Dn];
__device__ float g_v[(size_t)Bn*Nn*Dn];
__device__ float g_otmp[(size_t)Bn*Nn*Dn];

// ---------------------------------------------------------------------------
// mma.sync bf16-split NT GEMM: C[m,o] = sum_k A[m,k] * W[o,k]
// CTA tile 128m x 128n, 8 warps each 64x32 (4x4 m16n8k16 tiles), K chunks of 32.
// D = Ah.Bh + Ah.Bl + Al.Bh  (3-way split; lo*lo term ~2^-16, dropped)
// ---------------------------------------------------------------------------
#define GKC 32
#define GST 40        // smem row stride in halfs (80 B) — conflict-free for ldmatrix

__device__ __forceinline__ void ldsm_x4(uint32_t r[4], uint32_t addr) {
    asm volatile("ldmatrix.sync.aligned.m8n8.x4.shared.b16 {%0,%1,%2,%3}, [%4];"
                 : "=r"(r[0]), "=r"(r[1]), "=r"(r[2]), "=r"(r[3]) : "r"(addr));
}
__device__ __forceinline__ void ldsm_x2(uint32_t r[2], uint32_t addr) {
    asm volatile("ldmatrix.sync.aligned.m8n8.x2.shared.b16 {%0,%1}, [%2];"
                 : "=r"(r[0]), "=r"(r[1]) : "r"(addr));
}
__device__ __forceinline__ void mma_bf16(float c[4], const uint32_t a[4], const uint32_t b[2]) {
    asm volatile("mma.sync.aligned.m16n8k16.row.col.f32.bf16.bf16.f32 "
                 "{%0,%1,%2,%3}, {%4,%5,%6,%7}, {%8,%9}, {%0,%1,%2,%3};"
                 : "+f"(c[0]), "+f"(c[1]), "+f"(c[2]), "+f"(c[3])
                 : "r"(a[0]), "r"(a[1]), "r"(a[2]), "r"(a[3]), "r"(b[0]), "r"(b[1]));
}

// split 8 floats (two float4) into 4 packed-hi u32 + 4 packed-lo u32
__device__ __forceinline__ void split8(float4 v0, float4 v1, uint32_t* h, uint32_t* l) {
    asm("cvt.rn.bf16x2.f32 %0, %1, %2;" : "=r"(h[0]) : "f"(v0.y), "f"(v0.x));
    asm("cvt.rn.bf16x2.f32 %0, %1, %2;" : "=r"(h[1]) : "f"(v0.w), "f"(v0.z));
    asm("cvt.rn.bf16x2.f32 %0, %1, %2;" : "=r"(h[2]) : "f"(v1.y), "f"(v1.x));
    asm("cvt.rn.bf16x2.f32 %0, %1, %2;" : "=r"(h[3]) : "f"(v1.w), "f"(v1.z));
    float a0 = __uint_as_float(h[0] << 16), b0 = __uint_as_float(h[0] & 0xffff0000u);
    float a1 = __uint_as_float(h[1] << 16), b1 = __uint_as_float(h[1] & 0xffff0000u);
    float a2 = __uint_as_float(h[2] << 16), b2 = __uint_as_float(h[2] & 0xffff0000u);
    float a3 = __uint_as_float(h[3] << 16), b3 = __uint_as_float(h[3] & 0xffff0000u);
    asm("cvt.rn.bf16x2.f32 %0, %1, %2;" : "=r"(l[0]) : "f"(v0.y - b0), "f"(v0.x - a0));
    asm("cvt.rn.bf16x2.f32 %0, %1, %2;" : "=r"(l[1]) : "f"(v0.w - b1), "f"(v0.z - a1));
    asm("cvt.rn.bf16x2.f32 %0, %1, %2;" : "=r"(l[2]) : "f"(v1.y - b2), "f"(v1.x - a2));
    asm("cvt.rn.bf16x2.f32 %0, %1, %2;" : "=r"(l[3]) : "f"(v1.w - b3), "f"(v1.z - a3));
}

template<int MODE>
__global__ __launch_bounds__(256) void gemm_mma(const float* __restrict__ A,
                                                const float* __restrict__ Wm,
                                                const float* __restrict__ bias,
                                                float* __restrict__ Cout)
{
    __shared__ __align__(16) __nv_bfloat16 sAh[128*GST], sAl[128*GST];
    __shared__ __align__(16) __nv_bfloat16 sBh[128*GST], sBl[128*GST];

    const int tid = threadIdx.x;
    const int lane = tid & 31;
    const int wid = tid >> 5;
    const int wm = wid & 1;            // 2 m-blocks of 64
    const int wn = wid >> 1;           // 4 n-blocks of 32
    const int m0 = blockIdx.y * 128;
    const int n0 = blockIdx.x * 128;

    const float* Asrc = (MODE == 3) ? (const float*)g_otmp : A;

    float acc[4][4][4];
#pragma unroll
    for (int mt = 0; mt < 4; mt++)
#pragma unroll
        for (int nt = 0; nt < 4; nt++)
#pragma unroll
            for (int q = 0; q < 4; q++) acc[mt][nt][q] = 0.f;

    const int frow = tid >> 1;            // 0..127
    const int fkc  = (tid & 1) * 16;      // 0 or 16

    // ldmatrix base addresses (bytes)
    const uint32_t aAh = smem_u32(sAh), aAl = smem_u32(sAl);
    const uint32_t aBh = smem_u32(sBh), aBl = smem_u32(sBl);
    const uint32_t aoffA = (uint32_t)((wm*64 + (lane & 15)) * GST + (lane >> 4) * 8) * 2;
    const uint32_t aoffB = (uint32_t)((wn*32 + (lane & 7)) * GST + ((lane >> 3) & 1) * 8) * 2;

    for (int ch = 0; ch < 16; ch++) {
        const int k0 = ch * GKC;
        __syncthreads();
        // ---- fill: split A(128x32) and B(128x32) into hi/lo bf16 smem ----
        {
            const float* as = Asrc + (size_t)(m0 + frow) * Dn + k0 + fkc;
            float4 x0 = *(const float4*)(as);
            float4 x1 = *(const float4*)(as + 4);
            float4 x2 = *(const float4*)(as + 8);
            float4 x3 = *(const float4*)(as + 12);
            uint32_t h[8], l[8];
            split8(x0, x1, h, l);
            split8(x2, x3, h + 4, l + 4);
            const int so = frow * GST + fkc;
            *(uint4*)&sAh[so]     = make_uint4(h[0], h[1], h[2], h[3]);
            *(uint4*)&sAh[so + 8] = make_uint4(h[4], h[5], h[6], h[7]);
            *(uint4*)&sAl[so]     = make_uint4(l[0], l[1], l[2], l[3]);
            *(uint4*)&sAl[so + 8] = make_uint4(l[4], l[5], l[6], l[7]);

            const float* bs = Wm + (size_t)(n0 + frow) * Dn + k0 + fkc;
            float4 y0 = *(const float4*)(bs);
            float4 y1 = *(const float4*)(bs + 4);
            float4 y2 = *(const float4*)(bs + 8);
            float4 y3 = *(const float4*)(bs + 12);
            split8(y0, y1, h, l);
            split8(y2, y3, h + 4, l + 4);
            *(uint4*)&sBh[so]     = make_uint4(h[0], h[1], h[2], h[3]);
            *(uint4*)&sBh[so + 8] = make_uint4(h[4], h[5], h[6], h[7]);
            *(uint4*)&sBl[so]     = make_uint4(l[0], l[1], l[2], l[3]);
            *(uint4*)&sBl[so + 8] = make_uint4(l[4], l[5], l[6], l[7]);
        }
        __syncthreads();

        // ---- MMA: 2 k16-steps per chunk ----
#pragma unroll
        for (int ks = 0; ks < 2; ks++) {
            const uint32_t kso = (uint32_t)(ks * 16 * 2);   // 32 B
            uint32_t ah[4][4], al[4][4];
#pragma unroll
            for (int mt = 0; mt < 4; mt++) {
                const uint32_t ro = (uint32_t)(mt * 16 * GST * 2);
                ldsm_x4(ah[mt], aAh + aoffA + ro + kso);
                ldsm_x4(al[mt], aAl + aoffA + ro + kso);
            }
            uint32_t bh[4][2], bl[4][2];
#pragma unroll
            for (int nt = 0; nt < 4; nt++) {
                const uint32_t ro = (uint32_t)(nt * 8 * GST * 2);
                ldsm_x2(bh[nt], aBh + aoffB + ro + kso);
                ldsm_x2(bl[nt], aBl + aoffB + ro + kso);
            }
#pragma unroll
            for (int mt = 0; mt < 4; mt++)
#pragma unroll
                for (int nt = 0; nt < 4; nt++) {
                    mma_bf16(acc[mt][nt], ah[mt], bh[nt]);
                    mma_bf16(acc[mt][nt], ah[mt], bl[nt]);
                    mma_bf16(acc[mt][nt], al[mt], bh[nt]);
                }
        }
    }

    // ---- epilogue ----
    float* dst = (MODE == 0) ? g_q : (MODE == 1) ? g_k : (MODE == 2) ? g_v : Cout;
#pragma unroll
    for (int mt = 0; mt < 4; mt++) {
#pragma unroll
        for (int nt = 0; nt < 4; nt++) {
            const int row0 = m0 + wm*64 + mt*16 + (lane >> 2);
            const int col  = n0 + wn*32 + nt*8 + (lane & 3) * 2;
            float2 v0 = make_float2(acc[mt][nt][0], acc[mt][nt][1]);
            float2 v1 = make_float2(acc[mt][nt][2], acc[mt][nt][3]);
            if (MODE == 3) {
                v0.x += bias[col]; v0.y += bias[col + 1];
                v1.x += bias[col]; v1.y += bias[col + 1];
            }
            *(float2*)&dst[(size_t)row0 * Dn + col]       = v0;
            *(float2*)&dst[(size_t)(row0 + 8) * Dn + col] = v1;
        }
    }
}

// ---------------------------------------------------------------------------
// Fused flash attention (R11-best; q/k/v layout [b, n, H*dh]: row stride Dn).
// ---------------------------------------------------------------------------
#define JT 256
#define WIN 319
#define QS_ST 68
#define KS_ST 260
#define VS_ST 64
#define ES_ST 320
#define PS_ST 260
#define SM_KS_OFF (64*QS_ST)
#define SM_VS_OFF (SM_KS_OFF + 64*KS_ST)
#define SM_EP_OFF (SM_VS_OFF + JT*VS_ST)
#define SM_TOT    (SM_EP_OFF + 64*ES_ST)
#define SMEM_BYTES (SM_TOT * 4)

__global__ __launch_bounds__(256, 1) void flash_attn(const float* __restrict__ Eg,
                                                     const float* __restrict__ phase)
{
    extern __shared__ float sm[];
    float* Qs = sm;
    float* Ks = sm + SM_KS_OFF;
    float* Vs = sm + SM_VS_OFF;
    float* Es = sm + SM_EP_OFF;
    float* Ps = sm + SM_KS_OFF;
    float* Om = sm + SM_EP_OFF;

    const int bh = blockIdx.y;
    const int bb = bh >> 3, hh = bh & 7;
    const int i0 = blockIdx.x * 64;
    const int tid = threadIdx.x;
    const int tx = tid & 31;
    const int ty = tid >> 5;
    const int ib = ty * 8;
    const int jb = tx * 8;
    const int wb = jb - ib + 56;
    const int lane = tx;
    const int grp  = ty;
    const int tk  = tx >> 3;
    const int c0  = (tx & 7) * 4;

    const float* qg = g_q + ((size_t)bb * Nn + i0) * Dn + hh * DHn;
    const float* kg = g_k + (size_t)bb * Nn * Dn + hh * DHn;
    const float* vg = g_v + (size_t)bb * Nn * Dn + hh * DHn;

#pragma unroll
    for (int u = 0; u < 4; u++) {
        const int r  = lane + (u & 1) * 32;
        const int c4 = grp * 4 + (u >> 1) * 32;
        float4 v = *(const float4*)(qg + (size_t)r * Dn + c4);
        Qs[(c4+0)*QS_ST + r] = v.x * SCALE; Qs[(c4+1)*QS_ST + r] = v.y * SCALE;
        Qs[(c4+2)*QS_ST + r] = v.z * SCALE; Qs[(c4+3)*QS_ST + r] = v.w * SCALE;
    }

    {
        const int l0 = 0 - i0 + 960;
#pragma unroll
        for (int u = 0; u < 20; u++) {
            const int r  = lane + (u % 10) * 32;
            const int c4 = grp * 4 + (u / 10) * 32;
            if (r < WIN) {
                float4 v = *(const float4*)(Eg + (size_t)(l0 + r) * DHn + c4);
                Es[(c4+0)*ES_ST + r] = v.x; Es[(c4+1)*ES_ST + r] = v.y;
                Es[(c4+2)*ES_ST + r] = v.z; Es[(c4+3)*ES_ST + r] = v.w;
            }
        }
    }

    ull o_acc[8][4];
    float m_i[8], l_i[8];
#pragma unroll
    for (int i = 0; i < 8; i++) {
        m_i[i] = -1e30f; l_i[i] = 0.f;
#pragma unroll
        for (int p = 0; p < 4; p++) o_acc[i][p] = 0ULL;
    }

    for (int j0 = 0; j0 < Nn; j0 += JT) {
        __syncthreads();

#pragma unroll
        for (int u = 0; u < 16; u++) {
            const int j  = lane + (u & 7) * 32;
            const int c4 = grp * 4 + (u >> 3) * 32;
            float4 v = *(const float4*)(kg + (size_t)(j0 + j) * Dn + c4);
            Ks[(c4+0)*KS_ST + j] = v.x; Ks[(c4+1)*KS_ST + j] = v.y;
            Ks[(c4+2)*KS_ST + j] = v.z; Ks[(c4+3)*KS_ST + j] = v.w;
        }
#pragma unroll
        for (int u = 0; u < 16; u++) {
            const int idx = tid + u * 256;
            const int row = idx >> 4, c4 = (idx & 15) * 4;
            *(float4*)(Vs + row * VS_ST + c4) =
                *(const float4*)(vg + (size_t)(j0 + row) * Dn + c4);
        }
        __syncthreads();

        ull sa[8][4];
#pragma unroll
        for (int i = 0; i < 8; i++)
#pragma unroll
            for (int p = 0; p < 4; p++) sa[i][p] = 0ULL;

#pragma unroll 4
        for (int d = 0; d < 64; d++) {
            float4 q0 = *(const float4*)(Qs + d * QS_ST + ib);
            float4 q1 = *(const float4*)(Qs + d * QS_ST + ib + 4);
            ulonglong2 kA = *(const ulonglong2*)(Ks + d * KS_ST + jb);
            ulonglong2 kB = *(const ulonglong2*)(Ks + d * KS_ST + jb + 4);
            float4 e0 = *(const float4*)(Es + d * ES_ST + wb);
            float4 e1 = *(const float4*)(Es + d * ES_ST + wb + 4);
            float4 e2 = *(const float4*)(Es + d * ES_ST + wb + 8);
            float4 e3 = *(const float4*)(Es + d * ES_ST + wb + 12);
            float e[16] = { e0.x,e0.y,e0.z,e0.w, e1.x,e1.y,e1.z,e1.w,
                            e2.x,e2.y,e2.z,e2.w, e3.x,e3.y,e3.z,e3.w };
            ull pa[8] = { pk2(q0.x,q0.x), pk2(q0.y,q0.y), pk2(q0.z,q0.z), pk2(q0.w,q0.w),
                          pk2(q1.x,q1.x), pk2(q1.y,q1.y), pk2(q1.z,q1.z), pk2(q1.w,q1.w) };
            ull pb[4] = { kA.x, kA.y, kB.x, kB.y };
            ull pr[14];
#pragma unroll
            for (int o = 0; o < 14; o++) pr[o] = pk2(e[o], e[o+1]);
#pragma unroll
            for (int i = 0; i < 8; i++)
#pragma unroll
                for (int p = 0; p < 4; p++) {
                    ull t = add2(pb[p], pr[2*p + 7 - i]);
                    sa[i][p] = fma2(pa[i], t, sa[i][p]);
                }
        }

        __syncthreads();

#pragma unroll
        for (int i = 0; i < 8; i++) {
            float2 v0 = unpk(sa[i][0]);
            float2 v1 = unpk(sa[i][1]);
            float2 v2 = unpk(sa[i][2]);
            float2 v3 = unpk(sa[i][3]);
            float mx = fmaxf(fmaxf(fmaxf(v0.x, v0.y), fmaxf(v1.x, v1.y)),
                             fmaxf(fmaxf(v2.x, v2.y), fmaxf(v3.x, v3.y)));
#pragma unroll
            for (int o = 16; o; o >>= 1)
                mx = fmaxf(mx, __shfl_xor_sync(0xffffffffu, mx, o));
            const float mn = fmaxf(m_i[i], mx);
            const float al = __expf(m_i[i] - mn);
            m_i[i] = mn;
            float f0 = __expf(v0.x - mn), f1 = __expf(v0.y - mn);
            float f2 = __expf(v1.x - mn), f3 = __expf(v1.y - mn);
            float f4 = __expf(v2.x - mn), f5 = __expf(v2.y - mn);
            float f6 = __expf(v3.x - mn), f7 = __expf(v3.y - mn);
            float sum = ((f0 + f1) + (f2 + f3)) + ((f4 + f5) + (f6 + f7));
#pragma unroll
            for (int o = 16; o; o >>= 1)
                sum += __shfl_xor_sync(0xffffffffu, sum, o);
            l_i[i] = l_i[i] * al + sum;
            const ull aa = pk2(al, al);
#pragma unroll
            for (int p = 0; p < 4; p++)
                o_acc[i][p] = fma2(aa, o_acc[i][p], 0ULL);
            *(float4*)(Ps + (ib+i) * PS_ST + jb)     = make_float4(f0, f1, f2, f3);
            *(float4*)(Ps + (ib+i) * PS_ST + jb + 4) = make_float4(f4, f5, f6, f7);
        }
        __syncthreads();

        if (j0 + JT < Nn) {
            const int l0n = (j0 + JT) - i0 + 960;
#pragma unroll
            for (int u = 0; u < 20; u++) {
                const int r  = lane + (u % 10) * 32;
                const int c4 = grp * 4 + (u / 10) * 32;
                if (r < WIN) {
                    float4 v = *(const float4*)(Eg + (size_t)(l0n + r) * DHn + c4);
                    Es[(c4+0)*ES_ST + r] = v.x; Es[(c4+1)*ES_ST + r] = v.y;
                    Es[(c4+2)*ES_ST + r] = v.z; Es[(c4+3)*ES_ST + r] = v.w;
                }
            }
        }

#pragma unroll 2
        for (int k4 = 0; k4 < 64; k4 += 4) {
            const int kk = tk * 64 + k4;
            float4 pv[8];
#pragma unroll
            for (int i = 0; i < 8; i++)
                pv[i] = *(const float4*)(Ps + (ib+i) * PS_ST + kk);
#pragma unroll
            for (int u = 0; u < 4; u++) {
                float4 va = *(const float4*)(Vs + (kk+u) * VS_ST + c0);
                float4 vb = *(const float4*)(Vs + (kk+u) * VS_ST + c0 + 32);
                const ull* wa = (const ull*)&va;
                const ull* wv = (const ull*)&vb;
#pragma unroll
                for (int i = 0; i < 8; i++) {
                    const float pf = (u == 0) ? pv[i].x : (u == 1) ? pv[i].y
                                   : (u == 2) ? pv[i].z : pv[i].w;
                    const ull pp = pk2(pf, pf);
                    o_acc[i][0] = fma2(pp, wa[0], o_acc[i][0]);
                    o_acc[i][1] = fma2(pp, wa[1], o_acc[i][1]);
                    o_acc[i][2] = fma2(pp, wv[0], o_acc[i][2]);
                    o_acc[i][3] = fma2(pp, wv[1], o_acc[i][3]);
                }
            }
        }
    }

    __syncthreads();
#pragma unroll
    for (int i = 0; i < 8; i++)
#pragma unroll
        for (int p = 0; p < 4; p++) {
            float2 v = unpk(o_acc[i][p]);
            const int col = (p < 2) ? (c0 + 2*p) : (c0 + 32 + 2*(p-2));
            *(float2*)(Om + ((tk * 64 + ib + i) * 64 + col)) = v;
        }
    __syncthreads();

    if (tk == 0) {
#pragma unroll
        for (int i = 0; i < 8; i++) {
            const int gi = i0 + ib + i;
            const float f = phase[(size_t)bh * Nn + gi] / l_i[i];
#pragma unroll
            for (int half = 0; half < 2; half++) {
                const int c = c0 + half * 32;
                float4 a0 = *(const float4*)(Om + ((ib + i) * 64 + c));
                float4 a1 = *(const float4*)(Om + ((64 + ib + i) * 64 + c));
                float4 a2 = *(const float4*)(Om + ((128 + ib + i) * 64 + c));
                float4 a3 = *(const float4*)(Om + ((192 + ib + i) * 64 + c));
                float4 o;
                o.x = ((a0.x + a1.x) + (a2.x + a3.x)) * f;
                o.y = ((a0.y + a1.y) + (a2.y + a3.y)) * f;
                o.z = ((a0.z + a1.z) + (a2.z + a3.z)) * f;
                o.w = ((a0.w + a1.w) + (a2.w + a3.w)) * f;
                *(float4*)&g_otmp[(size_t)(bb * Nn + gi) * Dn + hh * 64 + c] = o;
            }
        }
    }
}

// ---------------------------------------------------------------------------
extern "C" void kernel_launch(void* const* d_in, const int* in_sizes, int n_in,
                              void* d_out, int out_size)
{
    const float* x     = (const float*)d_in[0];
    const float* phase = (const float*)d_in[1];
    const float* E     = (const float*)d_in[2];
    const float* Wq    = (const float*)d_in[3];
    const float* Wk    = (const float*)d_in[4];
    const float* Wv    = (const float*)d_in[5];
    const float* Wo    = (const float*)d_in[6];
    const float* bo    = (const float*)d_in[7];
    float* out = (float*)d_out;

    static const bool s_init = []() {
        cudaFuncSetAttribute(flash_attn, cudaFuncAttributeMaxDynamicSharedMemorySize, SMEM_BYTES);
        return true;
    }();
    (void)s_init;

    dim3 gproj(Dn / 128, (Bn * Nn) / 128);   // (4, 64)

    gemm_mma<0><<<gproj, 256>>>(x, Wq, nullptr, nullptr);
    gemm_mma<1><<<gproj, 256>>>(x, Wk, nullptr, nullptr);
    gemm_mma<2><<<gproj, 256>>>(x, Wv, nullptr, nullptr);

    flash_attn<<<dim3(Nn / 64, BHn), 256, SMEM_BYTES>>>(E, phase);

    gemm_mma<3><<<gproj, 256>>>(nullptr, Wo, bo, out);
}

// round 15
// speedup vs baseline: 1.5727x; 1.5727x over previous
#include <cuda_runtime.h>
#include <cuda_bf16.h>
#include <cstdint>

// Problem constants
#define Bn 8
#define Nn 1024
#define Dn 512
#define Hn 8
#define DHn 64
#define BHn (Bn*Hn)          // 64
#define SCALE 0.125f         // 1/sqrt(64)

typedef unsigned long long ull;

__device__ __forceinline__ ull pk2(float lo, float hi) {
    ull r; asm("mov.b64 %0, {%1,%2};" : "=l"(r) : "f"(lo), "f"(hi)); return r;
}
__device__ __forceinline__ ull fma2(ull a, ull b, ull c) {
    ull d; asm("fma.rn.f32x2 %0, %1, %2, %3;" : "=l"(d) : "l"(a), "l"(b), "l"(c)); return d;
}
__device__ __forceinline__ ull add2(ull a, ull b) {
    ull d; asm("add.rn.f32x2 %0, %1, %2;" : "=l"(d) : "l"(a), "l"(b)); return d;
}
__device__ __forceinline__ float2 unpk(ull v) {
    float2 f; asm("mov.b64 {%0,%1}, %2;" : "=f"(f.x), "=f"(f.y) : "l"(v)); return f;
}
__device__ __forceinline__ uint32_t smem_u32(const void* p) {
    uint32_t a;
    asm("{ .reg .u64 t; cvta.to.shared.u64 t, %1; cvt.u32.u64 %0, t; }" : "=r"(a) : "l"(p));
    return a;
}

// Scratch (allocation-free rule: __device__ globals). f32 layout: [b, n, H*dh] = [8192, 512]
__device__ float g_q[(size_t)Bn*Nn*Dn];
__device__ float g_k[(size_t)Bn*Nn*Dn];
__device__ float g_v[(size_t)Bn*Nn*Dn];
__device__ float g_otmp[(size_t)Bn*Nn*Dn];
// bf16 hi/lo planes
__device__ __nv_bfloat16 g_xh[(size_t)Bn*Nn*Dn], g_xl[(size_t)Bn*Nn*Dn];
__device__ __nv_bfloat16 g_oh[(size_t)Bn*Nn*Dn], g_ol[(size_t)Bn*Nn*Dn];
__device__ __nv_bfloat16 g_wqh[Dn*Dn], g_wql[Dn*Dn];
__device__ __nv_bfloat16 g_wkh[Dn*Dn], g_wkl[Dn*Dn];
__device__ __nv_bfloat16 g_wvh[Dn*Dn], g_wvl[Dn*Dn];
__device__ __nv_bfloat16 g_woh[Dn*Dn], g_wol[Dn*Dn];

// ---------------------------------------------------------------------------
// Streaming split: f32 -> bf16 hi + bf16 lo (lo = x - hi)
// ---------------------------------------------------------------------------
__global__ __launch_bounds__(256) void convert_split(const float* __restrict__ src,
                                                     __nv_bfloat16* __restrict__ hi,
                                                     __nv_bfloat16* __restrict__ lo,
                                                     int n4)
{
    const int idx = blockIdx.x * 256 + threadIdx.x;
    if (idx >= n4) return;
    float4 v = ((const float4*)src)[idx];
    uint32_t h0, h1, l0, l1;
    asm("cvt.rn.bf16x2.f32 %0, %1, %2;" : "=r"(h0) : "f"(v.y), "f"(v.x));
    asm("cvt.rn.bf16x2.f32 %0, %1, %2;" : "=r"(h1) : "f"(v.w), "f"(v.z));
    float a0 = __uint_as_float(h0 << 16), b0 = __uint_as_float(h0 & 0xffff0000u);
    float a1 = __uint_as_float(h1 << 16), b1 = __uint_as_float(h1 & 0xffff0000u);
    asm("cvt.rn.bf16x2.f32 %0, %1, %2;" : "=r"(l0) : "f"(v.y - b0), "f"(v.x - a0));
    asm("cvt.rn.bf16x2.f32 %0, %1, %2;" : "=r"(l1) : "f"(v.w - b1), "f"(v.z - a1));
    ((uint2*)hi)[idx] = make_uint2(h0, h1);
    ((uint2*)lo)[idx] = make_uint2(l0, l1);
}

// ---------------------------------------------------------------------------
// bf16-split NT GEMM via mma.sync (fragment mapping validated in R14):
// C[m,o] = Ah.Bh + Ah.Bl + Al.Bh, CTA tile 128x128, K chunks of 32,
// register double-buffered fills (no conversion ALU in-kernel).
// ---------------------------------------------------------------------------
#define GKC 32
#define GST 40        // smem row stride in halfs (80 B)

__device__ __forceinline__ void ldsm_x4(uint32_t r[4], uint32_t addr) {
    asm volatile("ldmatrix.sync.aligned.m8n8.x4.shared.b16 {%0,%1,%2,%3}, [%4];"
                 : "=r"(r[0]), "=r"(r[1]), "=r"(r[2]), "=r"(r[3]) : "r"(addr));
}
__device__ __forceinline__ void ldsm_x2(uint32_t r[2], uint32_t addr) {
    asm volatile("ldmatrix.sync.aligned.m8n8.x2.shared.b16 {%0,%1}, [%2];"
                 : "=r"(r[0]), "=r"(r[1]) : "r"(addr));
}
__device__ __forceinline__ void mma_bf16(float c[4], const uint32_t a[4], const uint32_t b[2]) {
    asm volatile("mma.sync.aligned.m16n8k16.row.col.f32.bf16.bf16.f32 "
                 "{%0,%1,%2,%3}, {%4,%5,%6,%7}, {%8,%9}, {%0,%1,%2,%3};"
                 : "+f"(c[0]), "+f"(c[1]), "+f"(c[2]), "+f"(c[3])
                 : "r"(a[0]), "r"(a[1]), "r"(a[2]), "r"(a[3]), "r"(b[0]), "r"(b[1]));
}

template<int MODE>
__global__ __launch_bounds__(256) void gemm_bf16(const __nv_bfloat16* __restrict__ Ah_,
                                                 const __nv_bfloat16* __restrict__ Al_,
                                                 const __nv_bfloat16* __restrict__ Bh_,
                                                 const __nv_bfloat16* __restrict__ Bl_,
                                                 const float* __restrict__ bias,
                                                 float* __restrict__ Cout)
{
    __shared__ __align__(16) __nv_bfloat16 sAh[128*GST], sAl[128*GST];
    __shared__ __align__(16) __nv_bfloat16 sBh[128*GST], sBl[128*GST];

    const int tid = threadIdx.x;
    const int lane = tid & 31;
    const int wid = tid >> 5;
    const int wm = wid & 1;
    const int wn = wid >> 1;
    const int m0 = blockIdx.y * 128;
    const int n0 = blockIdx.x * 128;

    float acc[4][4][4];
#pragma unroll
    for (int mt = 0; mt < 4; mt++)
#pragma unroll
        for (int nt = 0; nt < 4; nt++)
#pragma unroll
            for (int q = 0; q < 4; q++) acc[mt][nt][q] = 0.f;

    const int frow = tid >> 1;            // 0..127
    const int fkh  = (tid & 1) * 16;      // half offset: 0 or 16

    const uint32_t aAh = smem_u32(sAh), aAl = smem_u32(sAl);
    const uint32_t aBh = smem_u32(sBh), aBl = smem_u32(sBl);
    const uint32_t aoffA = (uint32_t)((wm*64 + (lane & 15)) * GST + (lane >> 4) * 8) * 2;
    const uint32_t aoffB = (uint32_t)((wn*32 + (lane & 7)) * GST + ((lane >> 3) & 1) * 8) * 2;

    const size_t arow = (size_t)(m0 + frow) * Dn + fkh;
    const size_t brow = (size_t)(n0 + frow) * Dn + fkh;

    uint4 pAh[2], pAl[2], pBh[2], pBl[2];
    // prefetch chunk 0
    pAh[0] = *(const uint4*)(Ah_ + arow);      pAh[1] = *(const uint4*)(Ah_ + arow + 8);
    pAl[0] = *(const uint4*)(Al_ + arow);      pAl[1] = *(const uint4*)(Al_ + arow + 8);
    pBh[0] = *(const uint4*)(Bh_ + brow);      pBh[1] = *(const uint4*)(Bh_ + brow + 8);
    pBl[0] = *(const uint4*)(Bl_ + brow);      pBl[1] = *(const uint4*)(Bl_ + brow + 8);

    for (int ch = 0; ch < 16; ch++) {
        // ---- store current chunk to smem ----
        const int so = frow * GST + fkh;
        *(uint4*)&sAh[so] = pAh[0];  *(uint4*)&sAh[so + 8] = pAh[1];
        *(uint4*)&sAl[so] = pAl[0];  *(uint4*)&sAl[so + 8] = pAl[1];
        *(uint4*)&sBh[so] = pBh[0];  *(uint4*)&sBh[so + 8] = pBh[1];
        *(uint4*)&sBl[so] = pBl[0];  *(uint4*)&sBl[so + 8] = pBl[1];
        __syncthreads();

        // ---- prefetch next chunk (overlaps with ldsm/mma below) ----
        if (ch < 15) {
            const size_t ar = arow + (ch + 1) * GKC;
            const size_t br = brow + (ch + 1) * GKC;
            pAh[0] = *(const uint4*)(Ah_ + ar);  pAh[1] = *(const uint4*)(Ah_ + ar + 8);
            pAl[0] = *(const uint4*)(Al_ + ar);  pAl[1] = *(const uint4*)(Al_ + ar + 8);
            pBh[0] = *(const uint4*)(Bh_ + br);  pBh[1] = *(const uint4*)(Bh_ + br + 8);
            pBl[0] = *(const uint4*)(Bl_ + br);  pBl[1] = *(const uint4*)(Bl_ + br + 8);
        }

        // ---- MMA: 2 k16-steps per chunk ----
#pragma unroll
        for (int ks = 0; ks < 2; ks++) {
            const uint32_t kso = (uint32_t)(ks * 16 * 2);
            uint32_t ah[4][4], al[4][4];
#pragma unroll
            for (int mt = 0; mt < 4; mt++) {
                const uint32_t ro = (uint32_t)(mt * 16 * GST * 2);
                ldsm_x4(ah[mt], aAh + aoffA + ro + kso);
                ldsm_x4(al[mt], aAl + aoffA + ro + kso);
            }
            uint32_t bh[4][2], bl[4][2];
#pragma unroll
            for (int nt = 0; nt < 4; nt++) {
                const uint32_t ro = (uint32_t)(nt * 8 * GST * 2);
                ldsm_x2(bh[nt], aBh + aoffB + ro + kso);
                ldsm_x2(bl[nt], aBl + aoffB + ro + kso);
            }
#pragma unroll
            for (int mt = 0; mt < 4; mt++)
#pragma unroll
                for (int nt = 0; nt < 4; nt++) {
                    mma_bf16(acc[mt][nt], ah[mt], bh[nt]);
                    mma_bf16(acc[mt][nt], ah[mt], bl[nt]);
                    mma_bf16(acc[mt][nt], al[mt], bh[nt]);
                }
        }
        __syncthreads();
    }

    // ---- epilogue (validated in R14) ----
    float* dst = (MODE == 0) ? g_q : (MODE == 1) ? g_k : (MODE == 2) ? g_v : Cout;
#pragma unroll
    for (int mt = 0; mt < 4; mt++) {
#pragma unroll
        for (int nt = 0; nt < 4; nt++) {
            const int row0 = m0 + wm*64 + mt*16 + (lane >> 2);
            const int col  = n0 + wn*32 + nt*8 + (lane & 3) * 2;
            float2 v0 = make_float2(acc[mt][nt][0], acc[mt][nt][1]);
            float2 v1 = make_float2(acc[mt][nt][2], acc[mt][nt][3]);
            if (MODE == 3) {
                v0.x += bias[col]; v0.y += bias[col + 1];
                v1.x += bias[col]; v1.y += bias[col + 1];
            }
            *(float2*)&dst[(size_t)row0 * Dn + col]       = v0;
            *(float2*)&dst[(size_t)(row0 + 8) * Dn + col] = v1;
        }
    }
}

// ---------------------------------------------------------------------------
// Fused flash attention (R11-best; q/k/v layout [b, n, H*dh]: row stride Dn).
// ---------------------------------------------------------------------------
#define JT 256
#define WIN 319
#define QS_ST 68
#define KS_ST 260
#define VS_ST 64
#define ES_ST 320
#define PS_ST 260
#define SM_KS_OFF (64*QS_ST)
#define SM_VS_OFF (SM_KS_OFF + 64*KS_ST)
#define SM_EP_OFF (SM_VS_OFF + JT*VS_ST)
#define SM_TOT    (SM_EP_OFF + 64*ES_ST)
#define SMEM_BYTES (SM_TOT * 4)

__global__ __launch_bounds__(256, 1) void flash_attn(const float* __restrict__ Eg,
                                                     const float* __restrict__ phase)
{
    extern __shared__ float sm[];
    float* Qs = sm;
    float* Ks = sm + SM_KS_OFF;
    float* Vs = sm + SM_VS_OFF;
    float* Es = sm + SM_EP_OFF;
    float* Ps = sm + SM_KS_OFF;
    float* Om = sm + SM_EP_OFF;

    const int bh = blockIdx.y;
    const int bb = bh >> 3, hh = bh & 7;
    const int i0 = blockIdx.x * 64;
    const int tid = threadIdx.x;
    const int tx = tid & 31;
    const int ty = tid >> 5;
    const int ib = ty * 8;
    const int jb = tx * 8;
    const int wb = jb - ib + 56;
    const int lane = tx;
    const int grp  = ty;
    const int tk  = tx >> 3;
    const int c0  = (tx & 7) * 4;

    const float* qg = g_q + ((size_t)bb * Nn + i0) * Dn + hh * DHn;
    const float* kg = g_k + (size_t)bb * Nn * Dn + hh * DHn;
    const float* vg = g_v + (size_t)bb * Nn * Dn + hh * DHn;

#pragma unroll
    for (int u = 0; u < 4; u++) {
        const int r  = lane + (u & 1) * 32;
        const int c4 = grp * 4 + (u >> 1) * 32;
        float4 v = *(const float4*)(qg + (size_t)r * Dn + c4);
        Qs[(c4+0)*QS_ST + r] = v.x * SCALE; Qs[(c4+1)*QS_ST + r] = v.y * SCALE;
        Qs[(c4+2)*QS_ST + r] = v.z * SCALE; Qs[(c4+3)*QS_ST + r] = v.w * SCALE;
    }

    {
        const int l0 = 0 - i0 + 960;
#pragma unroll
        for (int u = 0; u < 20; u++) {
            const int r  = lane + (u % 10) * 32;
            const int c4 = grp * 4 + (u / 10) * 32;
            if (r < WIN) {
                float4 v = *(const float4*)(Eg + (size_t)(l0 + r) * DHn + c4);
                Es[(c4+0)*ES_ST + r] = v.x; Es[(c4+1)*ES_ST + r] = v.y;
                Es[(c4+2)*ES_ST + r] = v.z; Es[(c4+3)*ES_ST + r] = v.w;
            }
        }
    }

    ull o_acc[8][4];
    float m_i[8], l_i[8];
#pragma unroll
    for (int i = 0; i < 8; i++) {
        m_i[i] = -1e30f; l_i[i] = 0.f;
#pragma unroll
        for (int p = 0; p < 4; p++) o_acc[i][p] = 0ULL;
    }

    for (int j0 = 0; j0 < Nn; j0 += JT) {
        __syncthreads();

#pragma unroll
        for (int u = 0; u < 16; u++) {
            const int j  = lane + (u & 7) * 32;
            const int c4 = grp * 4 + (u >> 3) * 32;
            float4 v = *(const float4*)(kg + (size_t)(j0 + j) * Dn + c4);
            Ks[(c4+0)*KS_ST + j] = v.x; Ks[(c4+1)*KS_ST + j] = v.y;
            Ks[(c4+2)*KS_ST + j] = v.z; Ks[(c4+3)*KS_ST + j] = v.w;
        }
#pragma unroll
        for (int u = 0; u < 16; u++) {
            const int idx = tid + u * 256;
            const int row = idx >> 4, c4 = (idx & 15) * 4;
            *(float4*)(Vs + row * VS_ST + c4) =
                *(const float4*)(vg + (size_t)(j0 + row) * Dn + c4);
        }
        __syncthreads();

        ull sa[8][4];
#pragma unroll
        for (int i = 0; i < 8; i++)
#pragma unroll
            for (int p = 0; p < 4; p++) sa[i][p] = 0ULL;

#pragma unroll 4
        for (int d = 0; d < 64; d++) {
            float4 q0 = *(const float4*)(Qs + d * QS_ST + ib);
            float4 q1 = *(const float4*)(Qs + d * QS_ST + ib + 4);
            ulonglong2 kA = *(const ulonglong2*)(Ks + d * KS_ST + jb);
            ulonglong2 kB = *(const ulonglong2*)(Ks + d * KS_ST + jb + 4);
            float4 e0 = *(const float4*)(Es + d * ES_ST + wb);
            float4 e1 = *(const float4*)(Es + d * ES_ST + wb + 4);
            float4 e2 = *(const float4*)(Es + d * ES_ST + wb + 8);
            float4 e3 = *(const float4*)(Es + d * ES_ST + wb + 12);
            float e[16] = { e0.x,e0.y,e0.z,e0.w, e1.x,e1.y,e1.z,e1.w,
                            e2.x,e2.y,e2.z,e2.w, e3.x,e3.y,e3.z,e3.w };
            ull pa[8] = { pk2(q0.x,q0.x), pk2(q0.y,q0.y), pk2(q0.z,q0.z), pk2(q0.w,q0.w),
                          pk2(q1.x,q1.x), pk2(q1.y,q1.y), pk2(q1.z,q1.z), pk2(q1.w,q1.w) };
            ull pb[4] = { kA.x, kA.y, kB.x, kB.y };
            ull pr[14];
#pragma unroll
            for (int o = 0; o < 14; o++) pr[o] = pk2(e[o], e[o+1]);
#pragma unroll
            for (int i = 0; i < 8; i++)
#pragma unroll
                for (int p = 0; p < 4; p++) {
                    ull t = add2(pb[p], pr[2*p + 7 - i]);
                    sa[i][p] = fma2(pa[i], t, sa[i][p]);
                }
        }

        __syncthreads();

#pragma unroll
        for (int i = 0; i < 8; i++) {
            float2 v0 = unpk(sa[i][0]);
            float2 v1 = unpk(sa[i][1]);
            float2 v2 = unpk(sa[i][2]);
            float2 v3 = unpk(sa[i][3]);
            float mx = fmaxf(fmaxf(fmaxf(v0.x, v0.y), fmaxf(v1.x, v1.y)),
                             fmaxf(fmaxf(v2.x, v2.y), fmaxf(v3.x, v3.y)));
#pragma unroll
            for (int o = 16; o; o >>= 1)
                mx = fmaxf(mx, __shfl_xor_sync(0xffffffffu, mx, o));
            const float mn = fmaxf(m_i[i], mx);
            const float al = __expf(m_i[i] - mn);
            m_i[i] = mn;
            float f0 = __expf(v0.x - mn), f1 = __expf(v0.y - mn);
            float f2 = __expf(v1.x - mn), f3 = __expf(v1.y - mn);
            float f4 = __expf(v2.x - mn), f5 = __expf(v2.y - mn);
            float f6 = __expf(v3.x - mn), f7 = __expf(v3.y - mn);
            float sum = ((f0 + f1) + (f2 + f3)) + ((f4 + f5) + (f6 + f7));
#pragma unroll
            for (int o = 16; o; o >>= 1)
                sum += __shfl_xor_sync(0xffffffffu, sum, o);
            l_i[i] = l_i[i] * al + sum;
            const ull aa = pk2(al, al);
#pragma unroll
            for (int p = 0; p < 4; p++)
                o_acc[i][p] = fma2(aa, o_acc[i][p], 0ULL);
            *(float4*)(Ps + (ib+i) * PS_ST + jb)     = make_float4(f0, f1, f2, f3);
            *(float4*)(Ps + (ib+i) * PS_ST + jb + 4) = make_float4(f4, f5, f6, f7);
        }
        __syncthreads();

        if (j0 + JT < Nn) {
            const int l0n = (j0 + JT) - i0 + 960;
#pragma unroll
            for (int u = 0; u < 20; u++) {
                const int r  = lane + (u % 10) * 32;
                const int c4 = grp * 4 + (u / 10) * 32;
                if (r < WIN) {
                    float4 v = *(const float4*)(Eg + (size_t)(l0n + r) * DHn + c4);
                    Es[(c4+0)*ES_ST + r] = v.x; Es[(c4+1)*ES_ST + r] = v.y;
                    Es[(c4+2)*ES_ST + r] = v.z; Es[(c4+3)*ES_ST + r] = v.w;
                }
            }
        }

#pragma unroll 2
        for (int k4 = 0; k4 < 64; k4 += 4) {
            const int kk = tk * 64 + k4;
            float4 pv[8];
#pragma unroll
            for (int i = 0; i < 8; i++)
                pv[i] = *(const float4*)(Ps + (ib+i) * PS_ST + kk);
#pragma unroll
            for (int u = 0; u < 4; u++) {
                float4 va = *(const float4*)(Vs + (kk+u) * VS_ST + c0);
                float4 vb = *(const float4*)(Vs + (kk+u) * VS_ST + c0 + 32);
                const ull* wa = (const ull*)&va;
                const ull* wv = (const ull*)&vb;
#pragma unroll
                for (int i = 0; i < 8; i++) {
                    const float pf = (u == 0) ? pv[i].x : (u == 1) ? pv[i].y
                                   : (u == 2) ? pv[i].z : pv[i].w;
                    const ull pp = pk2(pf, pf);
                    o_acc[i][0] = fma2(pp, wa[0], o_acc[i][0]);
                    o_acc[i][1] = fma2(pp, wa[1], o_acc[i][1]);
                    o_acc[i][2] = fma2(pp, wv[0], o_acc[i][2]);
                    o_acc[i][3] = fma2(pp, wv[1], o_acc[i][3]);
                }
            }
        }
    }

    __syncthreads();
#pragma unroll
    for (int i = 0; i < 8; i++)
#pragma unroll
        for (int p = 0; p < 4; p++) {
            float2 v = unpk(o_acc[i][p]);
            const int col = (p < 2) ? (c0 + 2*p) : (c0 + 32 + 2*(p-2));
            *(float2*)(Om + ((tk * 64 + ib + i) * 64 + col)) = v;
        }
    __syncthreads();

    if (tk == 0) {
#pragma unroll
        for (int i = 0; i < 8; i++) {
            const int gi = i0 + ib + i;
            const float f = phase[(size_t)bh * Nn + gi] / l_i[i];
#pragma unroll
            for (int half = 0; half < 2; half++) {
                const int c = c0 + half * 32;
                float4 a0 = *(const float4*)(Om + ((ib + i) * 64 + c));
                float4 a1 = *(const float4*)(Om + ((64 + ib + i) * 64 + c));
                float4 a2 = *(const float4*)(Om + ((128 + ib + i) * 64 + c));
                float4 a3 = *(const float4*)(Om + ((192 + ib + i) * 64 + c));
                float4 o;
                o.x = ((a0.x + a1.x) + (a2.x + a3.x)) * f;
                o.y = ((a0.y + a1.y) + (a2.y + a3.y)) * f;
                o.z = ((a0.z + a1.z) + (a2.z + a3.z)) * f;
                o.w = ((a0.w + a1.w) + (a2.w + a3.w)) * f;
                *(float4*)&g_otmp[(size_t)(bb * Nn + gi) * Dn + hh * 64 + c] = o;
            }
        }
    }
}

// Device-symbol address helpers (host side must use cudaGetSymbolAddress? No —
// __device__ arrays can be referenced directly in kernel args via pointers taken
// in device code only. Instead we pass them through small launcher wrappers.)
__global__ void noop() {}

// ---------------------------------------------------------------------------
extern "C" void kernel_launch(void* const* d_in, const int* in_sizes, int n_in,
                              void* d_out, int out_size)
{
    const float* x     = (const float*)d_in[0];
    const float* phase = (const float*)d_in[1];
    const float* E     = (const float*)d_in[2];
    const float* Wq    = (const float*)d_in[3];
    const float* Wk    = (const float*)d_in[4];
    const float* Wv    = (const float*)d_in[5];
    const float* Wo    = (const float*)d_in[6];
    const float* bo    = (const float*)d_in[7];
    float* out = (float*)d_out;

    // Resolve device-global addresses once (host-callable, not an allocation)
    static __nv_bfloat16 *xh, *xl, *oh, *ol, *wqh, *wql, *wkh, *wkl, *wvh, *wvl, *woh, *wol;
    static float* otmp;
    static const bool s_init = []() {
        cudaFuncSetAttribute(flash_attn, cudaFuncAttributeMaxDynamicSharedMemorySize, SMEM_BYTES);
        cudaGetSymbolAddress((void**)&xh,  g_xh);  cudaGetSymbolAddress((void**)&xl,  g_xl);
        cudaGetSymbolAddress((void**)&oh,  g_oh);  cudaGetSymbolAddress((void**)&ol,  g_ol);
        cudaGetSymbolAddress((void**)&wqh, g_wqh); cudaGetSymbolAddress((void**)&wql, g_wql);
        cudaGetSymbolAddress((void**)&wkh, g_wkh); cudaGetSymbolAddress((void**)&wkl, g_wkl);
        cudaGetSymbolAddress((void**)&wvh, g_wvh); cudaGetSymbolAddress((void**)&wvl, g_wvl);
        cudaGetSymbolAddress((void**)&woh, g_woh); cudaGetSymbolAddress((void**)&wol, g_wol);
        cudaGetSymbolAddress((void**)&otmp, g_otmp);
        return true;
    }();
    (void)s_init;

    const int n4x = Bn * Nn * Dn / 4;     // 1,048,576
    const int n4w = Dn * Dn / 4;          // 65,536

    convert_split<<<(n4x + 255) / 256, 256>>>(x,  xh,  xl,  n4x);
    convert_split<<<(n4w + 255) / 256, 256>>>(Wq, wqh, wql, n4w);
    convert_split<<<(n4w + 255) / 256, 256>>>(Wk, wkh, wkl, n4w);
    convert_split<<<(n4w + 255) / 256, 256>>>(Wv, wvh, wvl, n4w);
    convert_split<<<(n4w + 255) / 256, 256>>>(Wo, woh, wol, n4w);

    dim3 gproj(Dn / 128, (Bn * Nn) / 128);   // (4, 64)
    gemm_bf16<0><<<gproj, 256>>>(xh, xl, wqh, wql, nullptr, nullptr);
    gemm_bf16<1><<<gproj, 256>>>(xh, xl, wkh, wkl, nullptr, nullptr);
    gemm_bf16<2><<<gproj, 256>>>(xh, xl, wvh, wvl, nullptr, nullptr);

    flash_attn<<<dim3(Nn / 64, BHn), 256, SMEM_BYTES>>>(E, phase);

    convert_split<<<(n4x + 255) / 256, 256>>>(otmp, oh, ol, n4x);
    gemm_bf16<3><<<gproj, 256>>>(oh, ol, woh, wol, bo, out);
}

// round 16
// speedup vs baseline: 2.2189x; 1.4109x over previous
#include <cuda_runtime.h>
#include <cuda_bf16.h>
#include <cstdint>

// Problem constants
#define Bn 8
#define Nn 1024
#define Dn 512
#define Hn 8
#define DHn 64
#define BHn (Bn*Hn)          // 64
#define SCALE 0.125f         // 1/sqrt(64)

typedef unsigned long long ull;

__device__ __forceinline__ ull pk2(float lo, float hi) {
    ull r; asm("mov.b64 %0, {%1,%2};" : "=l"(r) : "f"(lo), "f"(hi)); return r;
}
__device__ __forceinline__ ull fma2(ull a, ull b, ull c) {
    ull d; asm("fma.rn.f32x2 %0, %1, %2, %3;" : "=l"(d) : "l"(a), "l"(b), "l"(c)); return d;
}
__device__ __forceinline__ float2 unpk(ull v) {
    float2 f; asm("mov.b64 {%0,%1}, %2;" : "=f"(f.x), "=f"(f.y) : "l"(v)); return f;
}
__device__ __forceinline__ uint32_t smem_u32(const void* p) {
    uint32_t a;
    asm("{ .reg .u64 t; cvta.to.shared.u64 t, %1; cvt.u32.u64 %0, t; }" : "=r"(a) : "l"(p));
    return a;
}
// split two floats into packed bf16 hi pair + lo pair
__device__ __forceinline__ void split_pair(float x, float y, uint32_t& h, uint32_t& l) {
    asm("cvt.rn.bf16x2.f32 %0, %1, %2;" : "=r"(h) : "f"(y), "f"(x));
    float hx = __uint_as_float(h << 16);
    float hy = __uint_as_float(h & 0xffff0000u);
    asm("cvt.rn.bf16x2.f32 %0, %1, %2;" : "=r"(l) : "f"(y - hy), "f"(x - hx));
}

// Scratch: __device__ globals. f32 layout [b, n, H*dh] = [8192, 512]
__device__ float g_v[(size_t)Bn*Nn*Dn];
__device__ float g_otmp[(size_t)Bn*Nn*Dn];
// bf16 planes
__device__ __nv_bfloat16 g_qh[(size_t)Bn*Nn*Dn], g_ql[(size_t)Bn*Nn*Dn];
__device__ __nv_bfloat16 g_kh[(size_t)Bn*Nn*Dn], g_kl[(size_t)Bn*Nn*Dn];
__device__ __nv_bfloat16 g_xh[(size_t)Bn*Nn*Dn], g_xl[(size_t)Bn*Nn*Dn];
__device__ __nv_bfloat16 g_oh[(size_t)Bn*Nn*Dn], g_ol[(size_t)Bn*Nn*Dn];
__device__ __nv_bfloat16 g_wqh[Dn*Dn], g_wql[Dn*Dn];
__device__ __nv_bfloat16 g_wkh[Dn*Dn], g_wkl[Dn*Dn];
__device__ __nv_bfloat16 g_wvh[Dn*Dn], g_wvl[Dn*Dn];
__device__ __nv_bfloat16 g_woh[Dn*Dn], g_wol[Dn*Dn];
__device__ __nv_bfloat16 g_eh[2048*DHn], g_el[2048*DHn];   // el unused by flash

// ---------------------------------------------------------------------------
// Streaming split: f32 -> bf16 hi + bf16 lo (lo = x - hi)
// ---------------------------------------------------------------------------
__global__ __launch_bounds__(256) void convert_split(const float* __restrict__ src,
                                                     __nv_bfloat16* __restrict__ hi,
                                                     __nv_bfloat16* __restrict__ lo,
                                                     int n4)
{
    const int idx = blockIdx.x * 256 + threadIdx.x;
    if (idx >= n4) return;
    float4 v = ((const float4*)src)[idx];
    uint32_t h0, h1, l0, l1;
    split_pair(v.x, v.y, h0, l0);
    split_pair(v.z, v.w, h1, l1);
    ((uint2*)hi)[idx] = make_uint2(h0, h1);
    ((uint2*)lo)[idx] = make_uint2(l0, l1);
}

// ---------------------------------------------------------------------------
// bf16-split NT GEMM via mma.sync (R14-validated fragments)
// MODE 0/1: write bf16 hi/lo planes (q / k). MODE 2: write f32 g_v.
// MODE 3: write Cout + bias.
// ---------------------------------------------------------------------------
#define GKC 32
#define GST 40

__device__ __forceinline__ void ldsm_x4(uint32_t r[4], uint32_t addr) {
    asm volatile("ldmatrix.sync.aligned.m8n8.x4.shared.b16 {%0,%1,%2,%3}, [%4];"
                 : "=r"(r[0]), "=r"(r[1]), "=r"(r[2]), "=r"(r[3]) : "r"(addr));
}
__device__ __forceinline__ void ldsm_x2(uint32_t r[2], uint32_t addr) {
    asm volatile("ldmatrix.sync.aligned.m8n8.x2.shared.b16 {%0,%1}, [%2];"
                 : "=r"(r[0]), "=r"(r[1]) : "r"(addr));
}
__device__ __forceinline__ void mma_bf16(float c[4], const uint32_t a[4], const uint32_t b[2]) {
    asm volatile("mma.sync.aligned.m16n8k16.row.col.f32.bf16.bf16.f32 "
                 "{%0,%1,%2,%3}, {%4,%5,%6,%7}, {%8,%9}, {%0,%1,%2,%3};"
                 : "+f"(c[0]), "+f"(c[1]), "+f"(c[2]), "+f"(c[3])
                 : "r"(a[0]), "r"(a[1]), "r"(a[2]), "r"(a[3]), "r"(b[0]), "r"(b[1]));
}

template<int MODE>
__global__ __launch_bounds__(256) void gemm_bf16(const __nv_bfloat16* __restrict__ Ah_,
                                                 const __nv_bfloat16* __restrict__ Al_,
                                                 const __nv_bfloat16* __restrict__ Bh_,
                                                 const __nv_bfloat16* __restrict__ Bl_,
                                                 const float* __restrict__ bias,
                                                 float* __restrict__ Cout)
{
    __shared__ __align__(16) __nv_bfloat16 sAh[128*GST], sAl[128*GST];
    __shared__ __align__(16) __nv_bfloat16 sBh[128*GST], sBl[128*GST];

    const int tid = threadIdx.x;
    const int lane = tid & 31;
    const int wid = tid >> 5;
    const int wm = wid & 1;
    const int wn = wid >> 1;
    const int m0 = blockIdx.y * 128;
    const int n0 = blockIdx.x * 128;

    float acc[4][4][4];
#pragma unroll
    for (int mt = 0; mt < 4; mt++)
#pragma unroll
        for (int nt = 0; nt < 4; nt++)
#pragma unroll
            for (int q = 0; q < 4; q++) acc[mt][nt][q] = 0.f;

    const int frow = tid >> 1;
    const int fkh  = (tid & 1) * 16;

    const uint32_t aAh = smem_u32(sAh), aAl = smem_u32(sAl);
    const uint32_t aBh = smem_u32(sBh), aBl = smem_u32(sBl);
    const uint32_t aoffA = (uint32_t)((wm*64 + (lane & 15)) * GST + (lane >> 4) * 8) * 2;
    const uint32_t aoffB = (uint32_t)((wn*32 + (lane & 7)) * GST + ((lane >> 3) & 1) * 8) * 2;

    const size_t arow = (size_t)(m0 + frow) * Dn + fkh;
    const size_t brow = (size_t)(n0 + frow) * Dn + fkh;

    uint4 pAh[2], pAl[2], pBh[2], pBl[2];
    pAh[0] = *(const uint4*)(Ah_ + arow);  pAh[1] = *(const uint4*)(Ah_ + arow + 8);
    pAl[0] = *(const uint4*)(Al_ + arow);  pAl[1] = *(const uint4*)(Al_ + arow + 8);
    pBh[0] = *(const uint4*)(Bh_ + brow);  pBh[1] = *(const uint4*)(Bh_ + brow + 8);
    pBl[0] = *(const uint4*)(Bl_ + brow);  pBl[1] = *(const uint4*)(Bl_ + brow + 8);

    for (int ch = 0; ch < 16; ch++) {
        const int so = frow * GST + fkh;
        *(uint4*)&sAh[so] = pAh[0];  *(uint4*)&sAh[so + 8] = pAh[1];
        *(uint4*)&sAl[so] = pAl[0];  *(uint4*)&sAl[so + 8] = pAl[1];
        *(uint4*)&sBh[so] = pBh[0];  *(uint4*)&sBh[so + 8] = pBh[1];
        *(uint4*)&sBl[so] = pBl[0];  *(uint4*)&sBl[so + 8] = pBl[1];
        __syncthreads();

        if (ch < 15) {
            const size_t ar = arow + (ch + 1) * GKC;
            const size_t br = brow + (ch + 1) * GKC;
            pAh[0] = *(const uint4*)(Ah_ + ar);  pAh[1] = *(const uint4*)(Ah_ + ar + 8);
            pAl[0] = *(const uint4*)(Al_ + ar);  pAl[1] = *(const uint4*)(Al_ + ar + 8);
            pBh[0] = *(const uint4*)(Bh_ + br);  pBh[1] = *(const uint4*)(Bh_ + br + 8);
            pBl[0] = *(const uint4*)(Bl_ + br);  pBl[1] = *(const uint4*)(Bl_ + br + 8);
        }

#pragma unroll
        for (int ks = 0; ks < 2; ks++) {
            const uint32_t kso = (uint32_t)(ks * 16 * 2);
            uint32_t ah[4][4], al[4][4];
#pragma unroll
            for (int mt = 0; mt < 4; mt++) {
                const uint32_t ro = (uint32_t)(mt * 16 * GST * 2);
                ldsm_x4(ah[mt], aAh + aoffA + ro + kso);
                ldsm_x4(al[mt], aAl + aoffA + ro + kso);
            }
            uint32_t bh[4][2], bl[4][2];
#pragma unroll
            for (int nt = 0; nt < 4; nt++) {
                const uint32_t ro = (uint32_t)(nt * 8 * GST * 2);
                ldsm_x2(bh[nt], aBh + aoffB + ro + kso);
                ldsm_x2(bl[nt], aBl + aoffB + ro + kso);
            }
#pragma unroll
            for (int mt = 0; mt < 4; mt++)
#pragma unroll
                for (int nt = 0; nt < 4; nt++) {
                    mma_bf16(acc[mt][nt], ah[mt], bh[nt]);
                    mma_bf16(acc[mt][nt], ah[mt], bl[nt]);
                    mma_bf16(acc[mt][nt], al[mt], bh[nt]);
                }
        }
        __syncthreads();
    }

    // ---- epilogue ----
#pragma unroll
    for (int mt = 0; mt < 4; mt++) {
#pragma unroll
        for (int nt = 0; nt < 4; nt++) {
            const int row0 = m0 + wm*64 + mt*16 + (lane >> 2);
            const int col  = n0 + wn*32 + nt*8 + (lane & 3) * 2;
            if (MODE == 0 || MODE == 1) {
                __nv_bfloat16* dh = (MODE == 0) ? g_qh : g_kh;
                __nv_bfloat16* dl = (MODE == 0) ? g_ql : g_kl;
                uint32_t h0, l0, h1, l1;
                split_pair(acc[mt][nt][0], acc[mt][nt][1], h0, l0);
                split_pair(acc[mt][nt][2], acc[mt][nt][3], h1, l1);
                *(uint32_t*)&dh[(size_t)row0 * Dn + col]       = h0;
                *(uint32_t*)&dl[(size_t)row0 * Dn + col]       = l0;
                *(uint32_t*)&dh[(size_t)(row0 + 8) * Dn + col] = h1;
                *(uint32_t*)&dl[(size_t)(row0 + 8) * Dn + col] = l1;
            } else {
                float* dst = (MODE == 2) ? g_v : Cout;
                float2 v0 = make_float2(acc[mt][nt][0], acc[mt][nt][1]);
                float2 v1 = make_float2(acc[mt][nt][2], acc[mt][nt][3]);
                if (MODE == 3) {
                    v0.x += bias[col]; v0.y += bias[col + 1];
                    v1.x += bias[col]; v1.y += bias[col + 1];
                }
                *(float2*)&dst[(size_t)row0 * Dn + col]       = v0;
                *(float2*)&dst[(size_t)(row0 + 8) * Dn + col] = v1;
            }
        }
    }
}

// ---------------------------------------------------------------------------
// Flash attention: S + relative bias via mma.sync (bf16 split), softmax + AV fp32.
// Tile 64i x 128j, 256 threads.
// ---------------------------------------------------------------------------
#define JT 128
// smem byte offsets
#define OFF_QH 0
#define OFF_QL 9216
#define OFF_KH 18432
#define OFF_KL 36864
#define OFF_V  55296           // f32 [128][64]
#define OFF_EH 88064           // bf16 [192][72]
#define OFF_SS 115712          // f32 [64][132]  (S, then P in-place)
#define OFF_BT 149504          // f32 [64][200]
#define SMEM_F 200704
// strides
#define BSTRIDE 144            // bf16 row stride in bytes (72 halfs)
#define SS_ST 132
#define BT_ST 200

__global__ __launch_bounds__(256, 1) void flash_attn(const float* __restrict__ phase)
{
    extern __shared__ char smc[];
    float* sV  = (float*)(smc + OFF_V);
    float* sSS = (float*)(smc + OFF_SS);
    float* sBT = (float*)(smc + OFF_BT);
    float* sOM = (float*)(smc + OFF_KH);   // merge buffer aliases KH/KL/V (after last AV)

    const uint32_t uQH = smem_u32(smc + OFF_QH);
    const uint32_t uQL = smem_u32(smc + OFF_QL);
    const uint32_t uKH = smem_u32(smc + OFF_KH);
    const uint32_t uKL = smem_u32(smc + OFF_KL);
    const uint32_t uEH = smem_u32(smc + OFF_EH);

    const int bh = blockIdx.y;
    const int bb = bh >> 3, hh = bh & 7;
    const int i0 = blockIdx.x * 64;
    const int tid = threadIdx.x;
    const int lane = tid & 31;
    const int wid = tid >> 5;
    const int ib = wid * 8;            // softmax/AV rows
    const int jbs = lane * 4;          // softmax cols (128 = 32*4)
    const int tk = lane >> 3;          // AV k-quarter (32 each)
    const int c0 = (lane & 7) * 4;     // AV d-cols

    // ldmatrix per-lane offsets (R14-validated pattern, stride 72 halfs)
    const uint32_t offA = (uint32_t)((lane & 15) * 72 + (lane >> 4) * 8) * 2;
    const uint32_t offB = (uint32_t)((lane & 7) * 72 + ((lane >> 3) & 1) * 8) * 2;

    // ---- prologue: Q hi/lo tile 64x64 ----
#pragma unroll
    for (int u = 0; u < 4; u++) {
        const int idx = tid + u * 256;
        const int sub = idx & 511;
        const int row = sub >> 3, c = sub & 7;
        const __nv_bfloat16* src = ((u < 2) ? g_qh : g_ql)
            + ((size_t)(bb * Nn + i0 + row) * Dn + hh * DHn + c * 8);
        uint4 val = *(const uint4*)src;
        *(uint4*)(smc + ((u < 2) ? OFF_QH : OFF_QL) + (row * 72 + c * 8) * 2) = val;
    }

    ull o_acc[8][4];
    float m_i[8], l_i[8];
#pragma unroll
    for (int i = 0; i < 8; i++) {
        m_i[i] = -1e30f; l_i[i] = 0.f;
#pragma unroll
        for (int p = 0; p < 4; p++) o_acc[i][p] = 0ULL;
    }

    for (int j0 = 0; j0 < Nn; j0 += JT) {
        __syncthreads();   // prev AV done

        // ---- fills ----
        // K hi/lo: 128 rows x 8 chunks x 2 planes
#pragma unroll
        for (int u = 0; u < 8; u++) {
            const int idx = tid + u * 256;
            const int sub = idx & 1023;
            const int row = sub >> 3, c = sub & 7;
            const __nv_bfloat16* src = ((u < 4) ? g_kh : g_kl)
                + ((size_t)(bb * Nn + j0 + row) * Dn + hh * DHn + c * 8);
            uint4 val = *(const uint4*)src;
            *(uint4*)(smc + ((u < 4) ? OFF_KH : OFF_KL) + (row * 72 + c * 8) * 2) = val;
        }
        // V f32: 128 rows x 16 chunks
#pragma unroll
        for (int u = 0; u < 8; u++) {
            const int idx = tid + u * 256;
            const int row = idx >> 4, c4 = (idx & 15) * 4;
            *(float4*)(sV + row * 64 + c4) =
                *(const float4*)(g_v + (size_t)(bb * Nn + j0 + row) * Dn + hh * DHn + c4);
        }
        // E hi: 192 rows x 8 chunks (row clamp keeps in-bounds; col>190 unused)
        const int l0 = j0 - i0 + 960;
#pragma unroll
        for (int u = 0; u < 6; u++) {
            const int idx = tid + u * 256;
            const int row = idx >> 3, c = idx & 7;
            int lr = l0 + row; lr = (lr > 2046) ? 2046 : lr;
            uint4 val = *(const uint4*)(g_eh + (size_t)lr * DHn + c * 8);
            *(uint4*)(smc + OFF_EH + (row * 72 + c * 8) * 2) = val;
        }
        __syncthreads();

        // ---- pass 1: S = Qh.Kh + Qh.Kl + Ql.Kh (per warp: 64 x 16 cols) ----
        {
            float accS[4][2][4];
#pragma unroll
            for (int mt = 0; mt < 4; mt++)
#pragma unroll
                for (int nt = 0; nt < 2; nt++)
#pragma unroll
                    for (int q = 0; q < 4; q++) accS[mt][nt][q] = 0.f;
#pragma unroll
            for (int ks = 0; ks < 4; ks++) {
                const uint32_t kso = (uint32_t)(ks * 32);
                uint32_t qh[4][4], ql[4][4];
#pragma unroll
                for (int mt = 0; mt < 4; mt++) {
                    const uint32_t ro = (uint32_t)(mt * 16 * BSTRIDE);
                    ldsm_x4(qh[mt], uQH + offA + ro + kso);
                    ldsm_x4(ql[mt], uQL + offA + ro + kso);
                }
                uint32_t kh[2][2], kl[2][2];
#pragma unroll
                for (int nt = 0; nt < 2; nt++) {
                    const uint32_t ro = (uint32_t)((wid * 16 + nt * 8) * BSTRIDE);
                    ldsm_x2(kh[nt], uKH + offB + ro + kso);
                    ldsm_x2(kl[nt], uKL + offB + ro + kso);
                }
#pragma unroll
                for (int mt = 0; mt < 4; mt++)
#pragma unroll
                    for (int nt = 0; nt < 2; nt++) {
                        mma_bf16(accS[mt][nt], qh[mt], kh[nt]);
                        mma_bf16(accS[mt][nt], qh[mt], kl[nt]);
                        mma_bf16(accS[mt][nt], ql[mt], kh[nt]);
                    }
            }
#pragma unroll
            for (int mt = 0; mt < 4; mt++)
#pragma unroll
                for (int nt = 0; nt < 2; nt++) {
                    const int row = mt * 16 + (lane >> 2);
                    const int col = wid * 16 + nt * 8 + (lane & 3) * 2;
                    *(float2*)&sSS[row * SS_ST + col] =
                        make_float2(accS[mt][nt][0], accS[mt][nt][1]);
                    *(float2*)&sSS[(row + 8) * SS_ST + col] =
                        make_float2(accS[mt][nt][2], accS[mt][nt][3]);
                }
        }

        // ---- pass 2: Bt = (Qh + Ql).Eh (per warp: 64 x 24 cols of 192) ----
        {
            float accB[4][3][4];
#pragma unroll
            for (int mt = 0; mt < 4; mt++)
#pragma unroll
                for (int nt = 0; nt < 3; nt++)
#pragma unroll
                    for (int q = 0; q < 4; q++) accB[mt][nt][q] = 0.f;
#pragma unroll
            for (int ks = 0; ks < 4; ks++) {
                const uint32_t kso = (uint32_t)(ks * 32);
                uint32_t qh[4][4], ql[4][4];
#pragma unroll
                for (int mt = 0; mt < 4; mt++) {
                    const uint32_t ro = (uint32_t)(mt * 16 * BSTRIDE);
                    ldsm_x4(qh[mt], uQH + offA + ro + kso);
                    ldsm_x4(ql[mt], uQL + offA + ro + kso);
                }
                uint32_t eh[3][2];
#pragma unroll
                for (int nt = 0; nt < 3; nt++) {
                    const uint32_t ro = (uint32_t)((wid * 24 + nt * 8) * BSTRIDE);
                    ldsm_x2(eh[nt], uEH + offB + ro + kso);
                }
#pragma unroll
                for (int mt = 0; mt < 4; mt++)
#pragma unroll
                    for (int nt = 0; nt < 3; nt++) {
                        mma_bf16(accB[mt][nt], qh[mt], eh[nt]);
                        mma_bf16(accB[mt][nt], ql[mt], eh[nt]);
                    }
            }
#pragma unroll
            for (int mt = 0; mt < 4; mt++)
#pragma unroll
                for (int nt = 0; nt < 3; nt++) {
                    const int row = mt * 16 + (lane >> 2);
                    const int col = wid * 24 + nt * 8 + (lane & 3) * 2;
                    *(float2*)&sBT[row * BT_ST + col] =
                        make_float2(accB[mt][nt][0], accB[mt][nt][1]);
                    *(float2*)&sBT[(row + 8) * BT_ST + col] =
                        make_float2(accB[mt][nt][2], accB[mt][nt][3]);
                }
        }
        __syncthreads();

        // ---- fused softmax + P write (in-place over sSS) ----
#pragma unroll
        for (int i = 0; i < 8; i++) {
            const int row = ib + i;
            float4 sv = *(const float4*)&sSS[row * SS_ST + jbs];
            const int r0 = jbs - row + 63;
            float v0 = (sv.x + sBT[row * BT_ST + r0])     * SCALE;
            float v1 = (sv.y + sBT[row * BT_ST + r0 + 1]) * SCALE;
            float v2 = (sv.z + sBT[row * BT_ST + r0 + 2]) * SCALE;
            float v3 = (sv.w + sBT[row * BT_ST + r0 + 3]) * SCALE;
            float mx = fmaxf(fmaxf(v0, v1), fmaxf(v2, v3));
#pragma unroll
            for (int o = 16; o; o >>= 1)
                mx = fmaxf(mx, __shfl_xor_sync(0xffffffffu, mx, o));
            const float mn = fmaxf(m_i[i], mx);
            const float al = __expf(m_i[i] - mn);
            m_i[i] = mn;
            float f0 = __expf(v0 - mn), f1 = __expf(v1 - mn);
            float f2 = __expf(v2 - mn), f3 = __expf(v3 - mn);
            float sum = (f0 + f1) + (f2 + f3);
#pragma unroll
            for (int o = 16; o; o >>= 1)
                sum += __shfl_xor_sync(0xffffffffu, sum, o);
            l_i[i] = l_i[i] * al + sum;
            const ull aa = pk2(al, al);
#pragma unroll
            for (int p = 0; p < 4; p++)
                o_acc[i][p] = fma2(aa, o_acc[i][p], 0ULL);
            *(float4*)&sSS[row * SS_ST + jbs] = make_float4(f0, f1, f2, f3);
        }
        __syncthreads();

        // ---- AV fp32: O += P @ V (8i x 8d, k-quarter of 32) ----
#pragma unroll 2
        for (int k4 = 0; k4 < 32; k4 += 4) {
            const int kk = tk * 32 + k4;
            float4 pv[8];
#pragma unroll
            for (int i = 0; i < 8; i++)
                pv[i] = *(const float4*)&sSS[(ib + i) * SS_ST + kk];
#pragma unroll
            for (int u = 0; u < 4; u++) {
                float4 va = *(const float4*)(sV + (kk + u) * 64 + c0);
                float4 vb = *(const float4*)(sV + (kk + u) * 64 + c0 + 32);
                const ull* wa = (const ull*)&va;
                const ull* wv = (const ull*)&vb;
#pragma unroll
                for (int i = 0; i < 8; i++) {
                    const float pf = (u == 0) ? pv[i].x : (u == 1) ? pv[i].y
                                   : (u == 2) ? pv[i].z : pv[i].w;
                    const ull pp = pk2(pf, pf);
                    o_acc[i][0] = fma2(pp, wa[0], o_acc[i][0]);
                    o_acc[i][1] = fma2(pp, wa[1], o_acc[i][1]);
                    o_acc[i][2] = fma2(pp, wv[0], o_acc[i][2]);
                    o_acc[i][3] = fma2(pp, wv[1], o_acc[i][3]);
                }
            }
        }
    }

    // ---- merge 4 k-quarters (sOM aliases K/V region) and epilogue ----
    __syncthreads();
#pragma unroll
    for (int i = 0; i < 8; i++)
#pragma unroll
        for (int p = 0; p < 4; p++) {
            float2 v = unpk(o_acc[i][p]);
            const int col = (p < 2) ? (c0 + 2*p) : (c0 + 32 + 2*(p-2));
            *(float2*)(sOM + ((tk * 64 + ib + i) * 64 + col)) = v;
        }
    __syncthreads();

    if (tk == 0) {
#pragma unroll
        for (int i = 0; i < 8; i++) {
            const int gi = i0 + ib + i;
            const float f = phase[(size_t)bh * Nn + gi] / l_i[i];
#pragma unroll
            for (int half = 0; half < 2; half++) {
                const int c = c0 + half * 32;
                float4 a0 = *(const float4*)(sOM + ((ib + i) * 64 + c));
                float4 a1 = *(const float4*)(sOM + ((64 + ib + i) * 64 + c));
                float4 a2 = *(const float4*)(sOM + ((128 + ib + i) * 64 + c));
                float4 a3 = *(const float4*)(sOM + ((192 + ib + i) * 64 + c));
                float4 o;
                o.x = ((a0.x + a1.x) + (a2.x + a3.x)) * f;
                o.y = ((a0.y + a1.y) + (a2.y + a3.y)) * f;
                o.z = ((a0.z + a1.z) + (a2.z + a3.z)) * f;
                o.w = ((a0.w + a1.w) + (a2.w + a3.w)) * f;
                *(float4*)&g_otmp[(size_t)(bb * Nn + gi) * Dn + hh * 64 + c] = o;
            }
        }
    }
}

// ---------------------------------------------------------------------------
extern "C" void kernel_launch(void* const* d_in, const int* in_sizes, int n_in,
                              void* d_out, int out_size)
{
    const float* x     = (const float*)d_in[0];
    const float* phase = (const float*)d_in[1];
    const float* E     = (const float*)d_in[2];
    const float* Wq    = (const float*)d_in[3];
    const float* Wk    = (const float*)d_in[4];
    const float* Wv    = (const float*)d_in[5];
    const float* Wo    = (const float*)d_in[6];
    const float* bo    = (const float*)d_in[7];
    float* out = (float*)d_out;

    static __nv_bfloat16 *xh, *xl, *oh, *ol, *wqh, *wql, *wkh, *wkl, *wvh, *wvl, *woh, *wol, *eh, *el;
    static float* otmp;
    static const bool s_init = []() {
        cudaFuncSetAttribute(flash_attn, cudaFuncAttributeMaxDynamicSharedMemorySize, SMEM_F);
        cudaGetSymbolAddress((void**)&xh,  g_xh);  cudaGetSymbolAddress((void**)&xl,  g_xl);
        cudaGetSymbolAddress((void**)&oh,  g_oh);  cudaGetSymbolAddress((void**)&ol,  g_ol);
        cudaGetSymbolAddress((void**)&wqh, g_wqh); cudaGetSymbolAddress((void**)&wql, g_wql);
        cudaGetSymbolAddress((void**)&wkh, g_wkh); cudaGetSymbolAddress((void**)&wkl, g_wkl);
        cudaGetSymbolAddress((void**)&wvh, g_wvh); cudaGetSymbolAddress((void**)&wvl, g_wvl);
        cudaGetSymbolAddress((void**)&woh, g_woh); cudaGetSymbolAddress((void**)&wol, g_wol);
        cudaGetSymbolAddress((void**)&eh,  g_eh);  cudaGetSymbolAddress((void**)&el,  g_el);
        cudaGetSymbolAddress((void**)&otmp, g_otmp);
        return true;
    }();
    (void)s_init;

    const int n4x = Bn * Nn * Dn / 4;       // 1,048,576
    const int n4w = Dn * Dn / 4;            // 65,536
    const int n4e = (2 * Nn - 1) * DHn / 4; // 32,752

    convert_split<<<(n4x + 255) / 256, 256>>>(x,  xh,  xl,  n4x);
    convert_split<<<(n4w + 255) / 256, 256>>>(Wq, wqh, wql, n4w);
    convert_split<<<(n4w + 255) / 256, 256>>>(Wk, wkh, wkl, n4w);
    convert_split<<<(n4w + 255) / 256, 256>>>(Wv, wvh, wvl, n4w);
    convert_split<<<(n4w + 255) / 256, 256>>>(Wo, woh, wol, n4w);
    convert_split<<<(n4e + 255) / 256, 256>>>(E,  eh,  el,  n4e);

    dim3 gproj(Dn / 128, (Bn * Nn) / 128);   // (4, 64)
    gemm_bf16<0><<<gproj, 256>>>(xh, xl, wqh, wql, nullptr, nullptr);
    gemm_bf16<1><<<gproj, 256>>>(xh, xl, wkh, wkl, nullptr, nullptr);
    gemm_bf16<2><<<gproj, 256>>>(xh, xl, wvh, wvl, nullptr, nullptr);

    flash_attn<<<dim3(Nn / 64, BHn), 256, SMEM_F>>>(phase);

    convert_split<<<(n4x + 255) / 256, 256>>>(otmp, oh, ol, n4x);
    gemm_bf16<3><<<gproj, 256>>>(oh, ol, woh, wol, bo, out);
}